// round 5
// baseline (speedup 1.0000x reference)
#include <cuda_runtime.h>
#include <math.h>

#define BB 12
#define CC 64
#define KK 32
#define VV 32768
#define MID 32
#define RED 16

#define OUT_RF 0
#define OUT_SP (BB*KK*CC)                 /* 24576  */
#define OUT_ZO (OUT_SP + BB*VV)           /* 417792 */
#define OUT_LOSS (OUT_ZO + BB*CC*VV)      /* 25583616 */

// ------------------------ device scratch (static, no allocs) ------------------
__device__ unsigned g_maskbits[VV];
__device__ float g_msum[KK];
__device__ float g_A2[BB*CC*27*KK];       // [m=b*64+o][off*32+k]
__device__ float g_Wk[BB*KK];
__device__ float g_mod[BB*KK*CC];         // [b][k][c]
__device__ float g_dot[BB*MID], g_n1[BB*MID], g_n2[BB*MID];
__device__ float g_reg;

// ------------------------ init accumulators (every launch) --------------------
__global__ void k_init() {
    int t = threadIdx.x;
    if (t < BB*MID) { g_dot[t] = 0.f; g_n1[t] = 0.f; g_n2[t] = 0.f; }
    if (t == 0) g_reg = 0.f;
}

// ------------------------ mask bit-packing + sums -----------------------------
__global__ void k_maskbits(const float* __restrict__ masks) {
    int v = blockIdx.x * 256 + threadIdx.x;
    unsigned w = 0;
#pragma unroll
    for (int k = 0; k < KK; k++)
        if (masks[k*VV + v] > 0.5f) w |= (1u << k);
    g_maskbits[v] = w;
}

__global__ void k_msum(const float* __restrict__ masks) {
    int k = blockIdx.x;
    float s = 0.f;
    for (int v = threadIdx.x; v < VV; v += 256) s += masks[k*VV + v];
    __shared__ float sm[8];
#pragma unroll
    for (int o = 16; o; o >>= 1) s += __shfl_xor_sync(0xffffffffu, s, o);
    if ((threadIdx.x & 31) == 0) sm[threadIdx.x >> 5] = s;
    __syncthreads();
    if (threadIdx.x == 0) {
        float t = 0.f;
        for (int i = 0; i < 8; i++) t += sm[i];
        g_msum[k] = t;
    }
}

// ------------------------ rf[b,k,c] -------------------------------------------
__global__ __launch_bounds__(256) void k_rf(const float* __restrict__ Z,
                                            float* __restrict__ out) {
    int b = blockIdx.x / CC, c = blockIdx.x % CC;
    const float* z = Z + (size_t)blockIdx.x * VV;
    float acc[KK];
#pragma unroll
    for (int k = 0; k < KK; k++) acc[k] = 0.f;
    for (int v = threadIdx.x; v < VV; v += 256) {
        float zv = z[v];
        unsigned bits = g_maskbits[v];
#pragma unroll
        for (int k = 0; k < KK; k++)
            acc[k] += (bits & (1u << k)) ? zv : 0.f;
    }
    __shared__ float sm[8*KK];
    int lane = threadIdx.x & 31, warp = threadIdx.x >> 5;
#pragma unroll
    for (int k = 0; k < KK; k++) {
        float v = acc[k];
#pragma unroll
        for (int o = 16; o; o >>= 1) v += __shfl_xor_sync(0xffffffffu, v, o);
        if (lane == k) sm[warp*KK + k] = v;
    }
    __syncthreads();
    if (threadIdx.x < KK) {
        int k = threadIdx.x;
        float t = 0.f;
#pragma unroll
        for (int w = 0; w < 8; w++) t += sm[w*KK + k];
        out[OUT_RF + (b*KK + k)*CC + c] = t / (g_msum[k] + 1e-6f);
    }
}

// ------------------------ MMD / reg / Wk / mod (tiny, 1 block) ----------------
__global__ __launch_bounds__(384) void k_stats(const float* __restrict__ outbuf,
        const int* __restrict__ labels, const float* __restrict__ ages,
        const float* __restrict__ pw,
        const float* __restrict__ mw1, const float* __restrict__ mb1,
        const float* __restrict__ mw2, const float* __restrict__ mb2) {
    __shared__ float x2_s[KK*BB];
    __shared__ float d2_s[KK*BB*BB];
    __shared__ float dk_s[4*KK];
    __shared__ float Dm_s[KK], nm_s[KK], base_s[KK], af_s[BB];
    __shared__ int   labi[BB];
    __shared__ float cnt[3];
    const float* rf = outbuf + OUT_RF;
    int t = threadIdx.x;

    if (t < BB) labi[t] = labels[t];
    if (t < 3)  cnt[t] = 0.f;
    __syncthreads();
    if (t == 0) for (int i = 0; i < BB; i++) cnt[labi[i]] += 1.f;

    // x2[b,k]
    if (t < BB*KK) {
        int b = t / KK, k = t % KK;
        const float* r = rf + (b*KK + k)*CC;
        float s = 0.f;
        for (int c = 0; c < CC; c++) s += r[c]*r[c];
        x2_s[k*BB + b] = s;
    }
    __syncthreads();
    // d2[k,i,j]
    for (int e = t; e < KK*BB*BB; e += 384) {
        int k = e / (BB*BB), r = e % (BB*BB), i = r / BB, j = r % BB;
        const float* ri = rf + (i*KK + k)*CC;
        const float* rj = rf + (j*KK + k)*CC;
        float s = 0.f;
        for (int c = 0; c < CC; c++) s += ri[c]*rj[c];
        d2_s[e] = fmaxf(x2_s[k*BB + i] + x2_s[k*BB + j] - 2.f*s, 0.f);
    }
    __syncthreads();
    // MMD per (sigma, k)
    if (t < 4*KK) {
        int si = t / KK, k = t % KK;
        const float sig[4] = {0.1f, 0.5f, 1.0f, 2.0f};
        float inv = 1.f / (2.f * sig[si]*sig[si]);
        float S[9]; float dd[3];
        for (int i = 0; i < 9; i++) S[i] = 0.f;
        dd[0] = dd[1] = dd[2] = 0.f;
        for (int i = 0; i < BB; i++) {
            int la = labi[i];
            for (int j = 0; j < BB; j++) {
                float kv = expf(-d2_s[k*BB*BB + i*BB + j] * inv);
                S[la*3 + labi[j]] += kv;
                if (i == j) dd[la] += kv;
            }
        }
        const int pa[3] = {2, 1, 2}, pb[3] = {0, 0, 1};
        float psum = 0.f;
        for (int p = 0; p < 3; p++) {
            float m = cnt[pa[p]], n = cnt[pb[p]];
            float t1 = (S[pa[p]*3 + pa[p]] - dd[pa[p]]) / (m*(m - 1.f));
            float t2 = (S[pb[p]*3 + pb[p]] - dd[pb[p]]) / (n*(n - 1.f));
            float t3 = S[pa[p]*3 + pb[p]] * (-2.f / (m*n));
            psum += t1 + t2 + t3;
        }
        dk_s[si*KK + k] = psum;
    }
    __syncthreads();
    if (t < KK)
        Dm_s[t] = 0.25f*(dk_s[t] + dk_s[KK + t] + dk_s[2*KK + t] + dk_s[3*KK + t]);
    __syncthreads();
    if (t == 0) {
        float mx = Dm_s[0];
        for (int k = 1; k < KK; k++) mx = fmaxf(mx, Dm_s[k]);
        mx = fmaxf(mx, 1e-6f);
        for (int k = 0; k < KK; k++) nm_s[k] = fmaxf(Dm_s[k]/mx, 0.f);
        float mp = -1e30f, mq = -1e30f;
        for (int k = 0; k < KK; k++) { mp = fmaxf(mp, pw[k]); mq = fmaxf(mq, nm_s[k]); }
        float sp = 0.f, sq = 0.f;
        for (int k = 0; k < KK; k++) { sp += expf(pw[k]-mp); sq += expf(nm_s[k]-mq); }
        float lsp = mp + logf(sp), lsq = mq + logf(sq);
        float reg = 0.f;
        for (int k = 0; k < KK; k++) {
            float lpk = pw[k] - lsp, lqk = nm_s[k] - lsq;
            float p = expf(lpk), q = expf(lqk);
            reg += 0.5f*q*(lqk - lpk) + 0.5f*p*(lpk - lqk);
        }
        g_reg = reg / (float)KK;
    }
    __syncthreads();
    if (t < KK) base_s[t] = 0.7f*pw[t] + 0.3f*nm_s[t];
    if (t < BB) {
        float x = 0.1f*(ages[t] - 50.f);
        af_s[t] = 1.f + fmaxf(x, 0.f) + log1pf(expf(-fabsf(x)));
    }
    __syncthreads();
    // Wk: warp b handles its 32 regions
    {
        int b = t >> 5, lane = t & 31;
        float v = fminf(fmaxf(base_s[lane]*af_s[b], 0.f), 2.f);
        float m = v;
#pragma unroll
        for (int o = 16; o; o >>= 1) m = fmaxf(m, __shfl_xor_sync(0xffffffffu, m, o));
        float e = expf(v - m);
        float s = e;
#pragma unroll
        for (int o = 16; o; o >>= 1) s += __shfl_xor_sync(0xffffffffu, s, o);
        g_Wk[b*KK + lane] = e / s;
    }
    // mod[b,k,c]: thread per (b,k)
    {
        int b = t / KK, k = t % KK;
        float r[CC];
        const float* rr = rf + (b*KK + k)*CC;
        for (int c = 0; c < CC; c++) r[c] = rr[c];
        float h[RED];
#pragma unroll
        for (int q = 0; q < RED; q++) {
            float a = mb1[q];
            for (int c = 0; c < CC; c++) a += r[c]*mw1[q*CC + c];
            h[q] = fmaxf(a, 0.f);
        }
        for (int c = 0; c < CC; c++) {
            float a = mb2[c];
#pragma unroll
            for (int q = 0; q < RED; q++) a += h[q]*mw2[c*RED + q];
            g_mod[(b*KK + k)*CC + c] = fmaxf(a, 0.f) + log1pf(expf(-fabsf(a)));
        }
    }
}

// ------------------------ A2[b,o,off,k] ---------------------------------------
__global__ __launch_bounds__(256) void k_A2(const float* __restrict__ outbuf,
                                            const float* __restrict__ rw) {
    int m = blockIdx.x;                 // b*64 + o
    int b = m / CC, o = m % CC;
    __shared__ float rf_s[KK*CC];
    __shared__ float rw_s[CC*27];
    const float* rf = outbuf + OUT_RF + b*KK*CC;
    for (int i = threadIdx.x; i < KK*CC; i += 256) rf_s[i] = rf[i];
    for (int i = threadIdx.x; i < CC*27; i += 256) rw_s[i] = rw[o*CC*27 + i];
    __syncthreads();
    for (int t = threadIdx.x; t < 27*KK; t += 256) {
        int off = t / KK, k = t % KK;
        float a = 0.f;
        for (int c = 0; c < CC; c++) a += rf_s[k*CC + c] * rw_s[c*27 + off];
        g_A2[(size_t)m*(27*KK) + off*KK + k] = a;
    }
}

// ------------------------ Z_clean + ortho stats -------------------------------
__global__ __launch_bounds__(256) void k_zclean(const float* __restrict__ Z,
        const float* __restrict__ sw, const float* __restrict__ nw,
        const float* __restrict__ uw, float* __restrict__ out) {
    int b = blockIdx.y;
    int v = blockIdx.x*256 + threadIdx.x;
    __shared__ float sw_s[MID*CC], nw_s[MID*CC], uw_s[CC*MID];
    __shared__ float red[3*MID];
    for (int i = threadIdx.x; i < MID*CC; i += 256) {
        sw_s[i] = sw[i]; nw_s[i] = nw[i]; uw_s[i] = uw[i];
    }
    if (threadIdx.x < 3*MID) red[threadIdx.x] = 0.f;
    __syncthreads();
    float cs[MID], cn[MID];
#pragma unroll
    for (int o = 0; o < MID; o++) { cs[o] = 0.f; cn[o] = 0.f; }
    const float* zb = Z + (size_t)b*CC*VV;
    for (int c = 0; c < CC; c++) {
        float z = zb[(size_t)c*VV + v];
#pragma unroll
        for (int o = 0; o < MID; o++) {
            cs[o] += sw_s[o*CC + c]*z;
            cn[o] += nw_s[o*CC + c]*z;
        }
    }
    int lane = threadIdx.x & 31;
#pragma unroll
    for (int o = 0; o < MID; o++) {
        float d = cs[o]*cn[o], a = cs[o]*cs[o], e = cn[o]*cn[o];
#pragma unroll
        for (int s = 16; s; s >>= 1) {
            d += __shfl_xor_sync(0xffffffffu, d, s);
            a += __shfl_xor_sync(0xffffffffu, a, s);
            e += __shfl_xor_sync(0xffffffffu, e, s);
        }
        if (lane == 0) {
            atomicAdd(&red[o], d);
            atomicAdd(&red[MID + o], a);
            atomicAdd(&red[2*MID + o], e);
        }
    }
    __syncthreads();
    if (threadIdx.x < MID) {
        atomicAdd(&g_dot[b*MID + threadIdx.x], red[threadIdx.x]);
        atomicAdd(&g_n1[b*MID + threadIdx.x], red[MID + threadIdx.x]);
        atomicAdd(&g_n2[b*MID + threadIdx.x], red[2*MID + threadIdx.x]);
    }
    float* zo = out + OUT_ZO + (size_t)b*CC*VV + v;
#pragma unroll
    for (int half = 0; half < 2; half++) {
        float zc[32];
#pragma unroll
        for (int j = 0; j < 32; j++) zc[j] = 0.f;
#pragma unroll
        for (int o = 0; o < MID; o++) {
            float co = cs[o];
#pragma unroll
            for (int j = 0; j < 32; j++) zc[j] += uw_s[(half*32 + j)*MID + o]*co;
        }
#pragma unroll
        for (int j = 0; j < 32; j++) zo[(size_t)(half*32 + j)*VV] = zc[j];
    }
}

// ------------------------ spatial[b,v] ----------------------------------------
__global__ __launch_bounds__(256) void k_spatial(float* __restrict__ out) {
    int b = blockIdx.y;
    int v = blockIdx.x*256 + threadIdx.x;
    __shared__ float wk[KK];
    if (threadIdx.x < KK) wk[threadIdx.x] = g_Wk[b*KK + threadIdx.x];
    __syncthreads();
    unsigned bits = g_maskbits[v];
    float s = 0.f;
#pragma unroll
    for (int k = 0; k < KK; k++) s += (bits & (1u << k)) ? wk[k] : 0.f;
    out[OUT_SP + b*VV + v] = s;
}

// ------------------------ conv-as-GEMM + fused epilogue -----------------------
// Zrec[b,o,v] = sum_{off,k} A2[b,o,off,k] * mask[k, v + delta(off)]
// out[b,o,v] += 0.1 * Zrec * (sum_k mod[b,k,o]*mask[k,v]) * spatial[b,v]
__global__ __launch_bounds__(256) void k_conv(float* __restrict__ out) {
    int b = blockIdx.y;
    int n0 = blockIdx.x * 128;
    int tid = threadIdx.x;
    int ty = tid >> 5;     // 0..7  -> 8 channels each
    int tx = tid & 31;     // 0..31 -> 4 voxels each
    __shared__ float A_s[KK][CC];
    __shared__ float S_s[KK][128];
    __shared__ float mod_s[KK][CC];
    for (int i = tid; i < KK*CC; i += 256)
        mod_s[i >> 6][i & 63] = g_mod[b*KK*CC + i];
    float acc[8][4];
#pragma unroll
    for (int i = 0; i < 8; i++)
#pragma unroll
        for (int j = 0; j < 4; j++) acc[i][j] = 0.f;

    int d0 = n0 >> 10;
    for (int off = 0; off < 27; off++) {
        int dz = off/9 - 1, dy = (off/3)%3 - 1, dx = off%3 - 1;
        __syncthreads();
        for (int i = tid; i < KK*CC; i += 256) {
            int m = i >> 5, kk = i & 31;
            A_s[kk][m] = g_A2[(size_t)(b*CC + m)*(27*KK) + off*KK + kk];
        }
        {
            int vv = tid & 127, kh = tid >> 7;
            int vg = n0 + vv;
            int d = d0 + dz;
            int h = ((vg >> 5) & 31) + dy;
            int w = (vg & 31) + dx;
            unsigned word = 0;
            if ((unsigned)d < 32u && (unsigned)h < 32u && (unsigned)w < 32u)
                word = g_maskbits[(d << 10) + (h << 5) + w];
#pragma unroll
            for (int k = 0; k < 16; k++) {
                int kk = kh*16 + k;
                S_s[kk][vv] = (word & (1u << kk)) ? 1.f : 0.f;
            }
        }
        __syncthreads();
#pragma unroll
        for (int kk = 0; kk < KK; kk++) {
            float a[8];
#pragma unroll
            for (int i = 0; i < 8; i++) a[i] = A_s[kk][ty*8 + i];
            float4 sv = *(const float4*)&S_s[kk][tx*4];
#pragma unroll
            for (int i = 0; i < 8; i++) {
                acc[i][0] += a[i]*sv.x;
                acc[i][1] += a[i]*sv.y;
                acc[i][2] += a[i]*sv.z;
                acc[i][3] += a[i]*sv.w;
            }
        }
    }
    // epilogue: scale acc in place
    int vbase = n0 + tx*4;
#pragma unroll
    for (int j = 0; j < 4; j++) {
        int v = vbase + j;
        unsigned bits = g_maskbits[v];
        float m8[8];
#pragma unroll
        for (int i = 0; i < 8; i++) m8[i] = 0.f;
#pragma unroll
        for (int k = 0; k < KK; k++) {
            if (bits & (1u << k)) {
#pragma unroll
                for (int i = 0; i < 8; i++) m8[i] += mod_s[k][ty*8 + i];
            }
        }
        float sp = out[OUT_SP + b*VV + v];
#pragma unroll
        for (int i = 0; i < 8; i++) acc[i][j] *= 0.1f*m8[i]*sp;
    }
#pragma unroll
    for (int i = 0; i < 8; i++) {
        size_t addr = (size_t)OUT_ZO + ((size_t)(b*CC + ty*8 + i))*VV + vbase;
        float4 zc = *(float4*)(out + addr);
        zc.x += acc[i][0]; zc.y += acc[i][1];
        zc.z += acc[i][2]; zc.w += acc[i][3];
        *(float4*)(out + addr) = zc;
    }
}

// ------------------------ final scalar ----------------------------------------
__global__ void k_final(float* __restrict__ out) {
    int t = threadIdx.x;   // 384
    __shared__ float red[384];
    float n1 = sqrtf(g_n1[t]), n2 = sqrtf(g_n2[t]);
    float c = g_dot[t] / (fmaxf(n1, 1e-8f)*fmaxf(n2, 1e-8f));
    red[t] = fabsf(c);
    __syncthreads();
    if (t == 0) {
        float s = 0.f;
        for (int i = 0; i < 384; i++) s += red[i];
        out[OUT_LOSS] = g_reg + s/384.f;
    }
}

// ------------------------ launch ----------------------------------------------
extern "C" void kernel_launch(void* const* d_in, const int* in_sizes, int n_in,
                              void* d_out, int out_size) {
    const float* Z      = (const float*)d_in[0];
    const float* masks  = (const float*)d_in[1];
    const int*   labels = (const int*)  d_in[2];
    const float* ages   = (const float*)d_in[3];
    const float* pw     = (const float*)d_in[4];
    const float* sw     = (const float*)d_in[5];
    const float* nw     = (const float*)d_in[6];
    const float* uw     = (const float*)d_in[7];
    const float* rw     = (const float*)d_in[8];
    const float* mw1    = (const float*)d_in[9];
    const float* mb1    = (const float*)d_in[10];
    const float* mw2    = (const float*)d_in[11];
    const float* mb2    = (const float*)d_in[12];
    float* out = (float*)d_out;

    k_init<<<1, 384>>>();
    k_maskbits<<<VV/256, 256>>>(masks);
    k_msum<<<KK, 256>>>(masks);
    k_rf<<<BB*CC, 256>>>(Z, out);
    k_stats<<<1, 384>>>(out, labels, ages, pw, mw1, mb1, mw2, mb2);
    k_A2<<<BB*CC, 256>>>(out, rw);
    dim3 g5(VV/256, BB);
    k_zclean<<<g5, 256>>>(Z, sw, nw, uw, out);
    k_spatial<<<g5, 256>>>(out);
    dim3 g7(VV/128, BB);
    k_conv<<<g7, 256>>>(out);
    k_final<<<1, 384>>>(out);
}